// round 4
// baseline (speedup 1.0000x reference)
#include <cuda_runtime.h>
#include <math.h>

#define IN_DIM   256
#define OUT_DIM  512
#define MEM_LEN  131072
#define BETA     1.0f
#define MEM_N    ((long long)MEM_LEN * OUT_DIM)   // 67108864
#define MD_N     ((long long)MEM_LEN * IN_DIM)    // 33554432

// Scratch (no allocations allowed)
__device__ float        g_enc[OUT_DIM];
__device__ unsigned int g_min_bits;

// ---------------------------------------------------------------------------
// Kernel A: xnorm -> dense encoder -> log_softmax -> g_enc. 1 block, 128 thr.
// Also resets g_min_bits (must be re-initialized every graph replay).
// ---------------------------------------------------------------------------
__global__ void enc_kernel(const float* __restrict__ x,
                           const float* __restrict__ W,
                           const float* __restrict__ b,
                           const float* __restrict__ mean,
                           const float* __restrict__ stdv) {
    __shared__ float xn[IN_DIM];
    __shared__ float redm[4];
    __shared__ float reds[4];
    int t = threadIdx.x;                 // 0..127
    if (t == 0) g_min_bits = 0x7F800000u;   // +inf bits
    for (int i = t; i < IN_DIM; i += 128) {
        float s = stdv[i];
        xn[i] = (s == 0.0f) ? 0.0f : (x[i] - mean[i]) / s;
    }
    __syncthreads();

    const float4* W4 = (const float4*)W;     // (256, 512) row-major
    float4 acc = make_float4(0.f, 0.f, 0.f, 0.f);
#pragma unroll 8
    for (int i = 0; i < IN_DIM; i++) {
        float  xi = xn[i];
        float4 w  = __ldg(&W4[i * (OUT_DIM / 4) + t]);
        acc.x = fmaf(xi, w.x, acc.x);
        acc.y = fmaf(xi, w.y, acc.y);
        acc.z = fmaf(xi, w.z, acc.z);
        acc.w = fmaf(xi, w.w, acc.w);
    }
    float4 bb = __ldg(&((const float4*)b)[t]);
    acc.x += bb.x; acc.y += bb.y; acc.z += bb.z; acc.w += bb.w;

    float m = fmaxf(fmaxf(acc.x, acc.y), fmaxf(acc.z, acc.w));
#pragma unroll
    for (int o = 16; o; o >>= 1) m = fmaxf(m, __shfl_xor_sync(0xffffffffu, m, o));
    if ((t & 31) == 0) redm[t >> 5] = m;
    __syncthreads();
    m = fmaxf(fmaxf(redm[0], redm[1]), fmaxf(redm[2], redm[3]));

    float s = expf(acc.x - m) + expf(acc.y - m) + expf(acc.z - m) + expf(acc.w - m);
#pragma unroll
    for (int o = 16; o; o >>= 1) s += __shfl_xor_sync(0xffffffffu, s, o);
    if ((t & 31) == 0) reds[t >> 5] = s;
    __syncthreads();
    s = reds[0] + reds[1] + reds[2] + reds[3];

    float lse = m + logf(s);
    ((float4*)g_enc)[t] = make_float4(acc.x - lse, acc.y - lse,
                                      acc.z - lse, acc.w - lse);
}

// ---------------------------------------------------------------------------
// Fused big kernel, grid-stride persistent warps.
//
// Output contract: out[q] = S[q-1], where S = concat(memory, mem_data),
// out[0] = loss (written by finalize). All stores here are aligned STG.128:
// the +1 shift is realized by a lane-to-lane shfl_up carry of v.w, with
// lane 0 picking up the tile's predecessor element (one scalar LDG per tile,
// L1/L2-resident since a neighbor warp streams it anyway).
//
// Phase 1: warp-per-row of `memory` (512 floats): aligned float4 loads feed
//          both the L1-distance (vs senc in smem) and the shifted copy.
//          Row dist -> warp shuffle reduce -> running warp min.
// Phase 2: warp-per-512-float tile of `mem_data`, same shifted copy.
// Epilogue: one atomicMin(min-bits) per warp (dists >= 0 so uint order holds).
// ---------------------------------------------------------------------------
__global__ void big_kernel(const float* __restrict__ memory,
                           const float* __restrict__ mem_data,
                           float* __restrict__ out) {
    __shared__ float senc[OUT_DIM];
    int t = threadIdx.x;
    for (int i = t; i < OUT_DIM; i += blockDim.x) senc[i] = g_enc[i];
    __syncthreads();

    const int lane   = t & 31;
    const int wid    = blockIdx.x * (blockDim.x >> 5) + (t >> 5);
    const int nwarps = gridDim.x * (blockDim.x >> 5);

    float wmin = INFINITY;

    // ---------------- Phase 1: memory (dist + shifted copy) ----------------
    for (int row = wid; row < MEM_LEN; row += nwarps) {
        const float*  rsrc = memory + (size_t)row * OUT_DIM;
        const float4* src4 = (const float4*)rsrc;
        float*        outq = out + (size_t)row * OUT_DIM;   // group base out[512r+...]
        const bool first = (row == 0);

        float carry = 0.0f;
        if (lane == 0 && !first) carry = __ldg(rsrc - 1);

        float dist = 0.0f;
#pragma unroll
        for (int c = 0; c < 4; c++) {
            float4 v = __ldg(&src4[c * 32 + lane]);
            int k = c * 128 + 4 * lane;
            dist += fabsf(v.x - senc[k])     + fabsf(v.y - senc[k + 1])
                  + fabsf(v.z - senc[k + 2]) + fabsf(v.w - senc[k + 3]);

            float prev = __shfl_up_sync(0xffffffffu, v.w, 1);
            if (lane == 0) prev = carry;

            if (first && c == 0 && lane == 0) {
                // out[0] is the loss slot — store only out[1..3]
                outq[1] = v.x; outq[2] = v.y; outq[3] = v.z;
            } else {
                *(float4*)(outq + k) = make_float4(prev, v.x, v.y, v.z);
            }
            carry = __shfl_sync(0xffffffffu, v.w, 31);
        }
#pragma unroll
        for (int o = 16; o; o >>= 1)
            dist += __shfl_xor_sync(0xffffffffu, dist, o);
        wmin = fminf(wmin, dist);
    }

    // ---------------- Phase 2: mem_data shifted copy ----------------
    const long long NT = MD_N / 512;          // 65536 tiles
    for (long long tile = wid; tile < NT; tile += nwarps) {
        const float*  tsrc = mem_data + tile * 512;
        const float4* src4 = (const float4*)tsrc;
        float*        outq = out + (size_t)(MEM_N + tile * 512);

        float carry = 0.0f;
        if (lane == 0)
            carry = (tile == 0) ? __ldg(memory + MEM_N - 1) : __ldg(tsrc - 1);

#pragma unroll
        for (int c = 0; c < 4; c++) {
            float4 v = __ldg(&src4[c * 32 + lane]);
            float prev = __shfl_up_sync(0xffffffffu, v.w, 1);
            if (lane == 0) prev = carry;
            *(float4*)(outq + c * 128 + 4 * lane) = make_float4(prev, v.x, v.y, v.z);
            carry = __shfl_sync(0xffffffffu, v.w, 31);
        }
    }

    // trailing scalar: out[MEM_N + MD_N] = mem_data[MD_N-1]
    if (wid == 0 && lane == 0)
        out[(size_t)(MEM_N + MD_N)] = __ldg(mem_data + MD_N - 1);

    if (lane == 0)
        atomicMin(&g_min_bits, __float_as_uint(wmin));
}

// ---------------------------------------------------------------------------
// Kernel C: loss + conditional slot overwrite. Tiny.
// ---------------------------------------------------------------------------
__global__ void finalize_kernel(const float* __restrict__ x,
                                const int* __restrict__ countp,
                                float* __restrict__ out) {
    int t = threadIdx.x;                 // 0..511
    float loss = __uint_as_float(g_min_bits);
    if (t == 0) out[0] = loss;
    if (loss <= BETA) {
        int count = countp ? countp[0] : 5;
        int pos = count % MEM_LEN;
        if (pos < 0) pos += MEM_LEN;
        if (t < OUT_DIM)
            out[1 + (size_t)pos * OUT_DIM + t] = g_enc[t];
        if (t < IN_DIM)
            out[1 + (size_t)MEM_N + (size_t)pos * IN_DIM + t] = x[t];
    }
}

// ---------------------------------------------------------------------------
extern "C" void kernel_launch(void* const* d_in, const int* in_sizes, int n_in,
                              void* d_out, int out_size) {
    const float* x        = (const float*)d_in[0];
    const float* W_enc    = (const float*)d_in[1];
    const float* b_enc    = (const float*)d_in[2];
    const float* memory   = (const float*)d_in[3];
    const float* mem_data = (const float*)d_in[4];
    const float* mean     = (const float*)d_in[5];
    const float* stdv     = (const float*)d_in[6];
    const int*   countp   = (n_in > 7) ? (const int*)d_in[7] : nullptr;
    float* out = (float*)d_out;

    enc_kernel<<<1, 128>>>(x, W_enc, b_enc, mean, stdv);
    big_kernel<<<148 * 6, 256>>>(memory, mem_data, out);
    finalize_kernel<<<1, 512>>>(x, countp, out);
}